// round 16
// baseline (speedup 1.0000x reference)
#include <cuda_runtime.h>
#include <cuda_fp16.h>
#include <cstdint>

#define N_NODES 100000
#define N_EDGES 1600000
#define IN_F    256
#define HID     128
#define OUTF    64

// Scratch (device globals: allocation-free per harness rules)
__device__ __align__(16) __half g_xh[(size_t)N_NODES * IN_F];   // X (fp16)
__device__ __align__(16) __half g_h1h[(size_t)N_NODES * HID];   // X@W1 (fp16)
__device__ __align__(16) __half g_h2h[(size_t)N_NODES * HID];   // A @ h1 (fp16)
__device__ __align__(16) __half g_h4h[(size_t)N_NODES * OUTF];  // relu(.)@W2 (fp16)
__device__ __align__(16) __half g_w1h[HID * IN_F];              // W1^T (fp16, [n][k])
__device__ __align__(16) __half g_w2h[OUTF * HID];              // W2^T (fp16, [n][k])
__device__ int    g_cnt[N_NODES];                 // per-row count (reset by scan C)
__device__ int    g_off[N_NODES + 1];             // CSR offsets
__device__ int    g_cur[N_NODES];                 // scatter cursors
__device__ int    g_wk;                           // scatter work-steal counter
__device__ int2   g_ecv[N_EDGES];                 // CSR-ordered (col, val_bits)

#define NB_SCAN ((N_NODES + 255) / 256)           // 391
__device__ int    g_bsum[NB_SCAN];

__device__ __forceinline__ void mma_f16(float c[4], const uint32_t a[4], const uint32_t b[2]) {
    asm volatile(
        "mma.sync.aligned.m16n8k16.row.col.f32.f16.f16.f32 "
        "{%0,%1,%2,%3}, {%4,%5,%6,%7}, {%8,%9}, {%0,%1,%2,%3};"
        : "+f"(c[0]), "+f"(c[1]), "+f"(c[2]), "+f"(c[3])
        : "r"(a[0]), "r"(a[1]), "r"(a[2]), "r"(a[3]), "r"(b[0]), "r"(b[1]));
}

__device__ __forceinline__ void cp16(uint32_t dst_smem, const void* src, bool pred) {
    int sz = pred ? 16 : 0;
    asm volatile("cp.async.cg.shared.global [%0], [%1], 16, %2;"
                 :: "r"(dst_smem), "l"(src), "r"(sz));
}

// ===========================================================================
// Fused: CSR count (4 edges/thread, MLP=4) + X->fp16 + W1^T + W2^T converts
// ===========================================================================
#define N_EQ4        (N_EDGES / 4)                      // 400000 (exact)
#define CNT4_BLOCKS  ((N_EQ4 + 255) / 256)              // 1563
#define XCVT_BLOCKS  (N_NODES * IN_F / 4 / 256)         // 25000 (exact)
#define W1H_BLOCKS   (IN_F * HID / 4 / 256)             // 32 (exact)
#define W2H_BLOCKS   (HID * OUTF / 4 / 256)             // 8 (exact)

__global__ void csr_count_cvt_kernel(const int* __restrict__ row,
                                     const float* __restrict__ x,
                                     const float* __restrict__ w1,
                                     const float* __restrict__ w2) {
    int b = blockIdx.x;
    if (b < CNT4_BLOCKS) {
        int i = b * 256 + threadIdx.x;       // int4 index
        if (i < N_EQ4) {
            int4 r4 = ((const int4*)row)[i];
            atomicAdd(&g_cnt[r4.x], 1);
            atomicAdd(&g_cnt[r4.y], 1);
            atomicAdd(&g_cnt[r4.z], 1);
            atomicAdd(&g_cnt[r4.w], 1);
        }
    } else if (b < CNT4_BLOCKS + XCVT_BLOCKS) {
        int i = (b - CNT4_BLOCKS) * 256 + threadIdx.x;   // float4 index
        float4 v = ((const float4*)x)[i];
        __half2 h0 = __floats2half2_rn(v.x, v.y);
        __half2 h1 = __floats2half2_rn(v.z, v.w);
        ((__half2*)g_xh)[i * 2 + 0] = h0;
        ((__half2*)g_xh)[i * 2 + 1] = h1;
    } else if (b < CNT4_BLOCKS + XCVT_BLOCKS + W1H_BLOCKS) {
        int t = (b - CNT4_BLOCKS - XCVT_BLOCKS) * 256 + threadIdx.x;
        int o = t * 4;                       // = n*IN_F + k
        int n = o >> 8;
        int k = o & (IN_F - 1);
        __half2 h0 = __floats2half2_rn(__ldg(w1 + (size_t)k * HID + n),
                                       __ldg(w1 + (size_t)(k + 1) * HID + n));
        __half2 h1 = __floats2half2_rn(__ldg(w1 + (size_t)(k + 2) * HID + n),
                                       __ldg(w1 + (size_t)(k + 3) * HID + n));
        ((__half2*)(g_w1h + o))[0] = h0;
        ((__half2*)(g_w1h + o))[1] = h1;
    } else {
        int t = (b - CNT4_BLOCKS - XCVT_BLOCKS - W1H_BLOCKS) * 256 + threadIdx.x;
        int o = t * 4;                       // = n*HID + k
        int n = o >> 7;
        int k = o & (HID - 1);
        __half2 h0 = __floats2half2_rn(__ldg(w2 + (size_t)k * OUTF + n),
                                       __ldg(w2 + (size_t)(k + 1) * OUTF + n));
        __half2 h1 = __floats2half2_rn(__ldg(w2 + (size_t)(k + 2) * OUTF + n),
                                       __ldg(w2 + (size_t)(k + 3) * OUTF + n));
        ((__half2*)(g_w2h + o))[0] = h0;
        ((__half2*)(g_w2h + o))[1] = h1;
    }
}

// ===========================================================================
// Parallel scan: phase A (block sums), phase C (prefix-of-sums + local scan)
// ===========================================================================
__global__ __launch_bounds__(256) void scan_a_kernel() {
    __shared__ int red[256];
    int t = threadIdx.x;
    int i = blockIdx.x * 256 + t;
    red[t] = (i < N_NODES) ? g_cnt[i] : 0;
    __syncthreads();
#pragma unroll
    for (int d = 128; d > 0; d >>= 1) {
        if (t < d) red[t] += red[t + d];
        __syncthreads();
    }
    if (t == 0) g_bsum[blockIdx.x] = red[0];
}

__global__ __launch_bounds__(256) void scan_c_kernel() {
    __shared__ int s[256];
    __shared__ int bpre;
    int t = threadIdx.x;

    if (blockIdx.x == 0 && t == 0) g_wk = 0;   // reset scatter work counter

    // exclusive prefix of block sums (<= 391 ints, strided read + reduce)
    int partial = 0;
    for (int i = t; i < (int)blockIdx.x; i += 256) partial += g_bsum[i];
    s[t] = partial;
    __syncthreads();
#pragma unroll
    for (int d = 128; d > 0; d >>= 1) {
        if (t < d) s[t] += s[t + d];
        __syncthreads();
    }
    if (t == 0) bpre = s[0];
    __syncthreads();

    int i = blockIdx.x * 256 + t;
    int c = (i < N_NODES) ? g_cnt[i] : 0;
    s[t] = c;
    __syncthreads();
#pragma unroll
    for (int d = 1; d < 256; d <<= 1) {
        int add = (t >= d) ? s[t - d] : 0;
        __syncthreads();
        s[t] += add;
        __syncthreads();
    }
    if (i < N_NODES) {
        int off = bpre + s[t] - c;
        g_off[i] = off;
        g_cur[i] = off;
        g_cnt[i] = 0;                          // reset for next replay
        if (i == N_NODES - 1) g_off[N_NODES] = off + c;
    }
}

// ===========================================================================
// FUSED: gemm1 tiles (128M x 64N, 8 warps 4Mx2N, warp 32x32) + work-steal
// scatter. Smaller warp tile -> ~32 accum regs -> 3 CTAs/SM (24 warps).
//   g_h1h[M,128] = Xh[M,256] @ W1h^T
// ===========================================================================
#define GROW_W    20                        // words (uint32) per smem row
#define G1_AW     (128 * GROW_W)            // 2560 words (A: 128 rows)
#define G1_BW     (64 * GROW_W)             // 1280 words (B: 64 rows)
#define G1_STAGE  (G1_AW + G1_BW)           // 3840 words
#define G1_SMEM   (2 * G1_STAGE * 4)        // 30720 bytes
#define G1_ITERS  (IN_F / 32)               // 8
#define M_TILES   ((N_NODES + 127) / 128)   // 782
#define G1_BLOCKS (M_TILES * 2)             // 1564 (x2 N-halves)
#define EXTRA_SC  782
#define FUSED_GRID (G1_BLOCKS + EXTRA_SC)

__global__ __launch_bounds__(256, 3) void fused_gemm1_scatter_kernel(
        const int* __restrict__ row,
        const int* __restrict__ col,
        const float* __restrict__ vals) {
    extern __shared__ uint32_t smw[];
    __shared__ int sb;

    const int tid = threadIdx.x;

    if (blockIdx.x < G1_BLOCKS) {
        // ---- gemm1 role ----
        const int warp = tid >> 5;
        const int lane = tid & 31;
        const int wm   = warp >> 1;          // 0..3
        const int wn   = warp & 1;           // 0..1
        const int brow = (blockIdx.x >> 1) * 128;
        const int bn   = (blockIdx.x & 1) * 64;   // N-half offset
        const int grp  = lane >> 2;
        const int tig  = lane & 3;

        const uint32_t smem_base = (uint32_t)__cvta_generic_to_shared(smw);

        float c[2][4][4];
#pragma unroll
        for (int mt = 0; mt < 2; mt++)
#pragma unroll
            for (int nt = 0; nt < 4; nt++)
#pragma unroll
                for (int i = 0; i < 4; i++) c[mt][nt][i] = 0.f;

        auto issue = [&](int it) {
            int k0 = it * 32;                        // half index
            uint32_t st = smem_base + (uint32_t)(it & 1) * G1_STAGE * 4;
            // A: 128 rows x 4 chunks = 512 -> 2 per thread
#pragma unroll
            for (int i = 0; i < 2; i++) {
                int f  = tid + i * 256;
                int r  = f >> 2;                     // 0..127
                int ch = f & 3;                      // 16B chunk
                int gr = brow + r;
                bool ok = gr < N_NODES;
                const __half* asrc = g_xh + (size_t)(ok ? gr : 0) * IN_F + k0 + ch * 8;
                cp16(st + (uint32_t)(r * GROW_W + ch * 4) * 4, asrc, ok);
            }
            // B: 64 rows x 4 chunks = 256 -> 1 per thread
            {
                int r  = tid >> 2;                   // 0..63
                int ch = tid & 3;
                const __half* bsrc = g_w1h + (size_t)(bn + r) * IN_F + k0 + ch * 8;
                cp16(st + (uint32_t)(G1_AW + r * GROW_W + ch * 4) * 4, bsrc, true);
            }
            asm volatile("cp.async.commit_group;" ::: "memory");
        };

        issue(0);

        for (int it = 0; it < G1_ITERS; it++) {
            if (it + 1 < G1_ITERS) {
                issue(it + 1);
                asm volatile("cp.async.wait_group 1;" ::: "memory");
            } else {
                asm volatile("cp.async.wait_group 0;" ::: "memory");
            }
            __syncthreads();

            const uint32_t* As = smw + (it & 1) * G1_STAGE;
            const uint32_t* Bs = As + G1_AW;

#pragma unroll
            for (int ks = 0; ks < 2; ks++) {         // two k16 steps per BK=32
                int kw = ks * 8;
                uint32_t a[2][4], bfr[4][2];
#pragma unroll
                for (int mt = 0; mt < 2; mt++) {
                    int m0 = wm * 32 + mt * 16;
                    a[mt][0] = As[(m0 + grp) * GROW_W + kw + tig];
                    a[mt][1] = As[(m0 + grp + 8) * GROW_W + kw + tig];
                    a[mt][2] = As[(m0 + grp) * GROW_W + kw + 4 + tig];
                    a[mt][3] = As[(m0 + grp + 8) * GROW_W + kw + 4 + tig];
                }
#pragma unroll
                for (int nt = 0; nt < 4; nt++) {
                    int n0 = wn * 32 + nt * 8;
                    bfr[nt][0] = Bs[(n0 + grp) * GROW_W + kw + tig];
                    bfr[nt][1] = Bs[(n0 + grp) * GROW_W + kw + 4 + tig];
                }
#pragma unroll
                for (int mt = 0; mt < 2; mt++)
#pragma unroll
                    for (int nt = 0; nt < 4; nt++)
                        mma_f16(c[mt][nt], a[mt], bfr[nt]);
            }
            __syncthreads();
        }

#pragma unroll
        for (int mt = 0; mt < 2; mt++) {
            int r0 = brow + wm * 32 + mt * 16 + grp;
            int r1 = r0 + 8;
#pragma unroll
            for (int nt = 0; nt < 4; nt++) {
                int col2 = bn + wn * 32 + nt * 8 + 2 * tig;
                if (r0 < N_NODES)
                    *(__half2*)(g_h1h + (size_t)r0 * HID + col2) =
                        __floats2half2_rn(c[mt][nt][0], c[mt][nt][1]);
                if (r1 < N_NODES)
                    *(__half2*)(g_h1h + (size_t)r1 * HID + col2) =
                        __floats2half2_rn(c[mt][nt][2], c[mt][nt][3]);
            }
        }
    }

    // ---- scatter role (work-stealing; gemm CTAs fall through when done) ----
    for (;;) {
        __syncthreads();
        if (tid == 0) sb = atomicAdd(&g_wk, 1024);
        __syncthreads();
        int base = sb;
        if (base >= N_EDGES) return;
        int e0 = base + tid * 4;
        if (e0 < N_EDGES) {                  // N_EDGES % 4 == 0 -> whole quad valid
            int4   r4 = *(const int4*)(row + e0);
            int4   c4 = *(const int4*)(col + e0);
            float4 v4 = *(const float4*)(vals + e0);
            int p0 = atomicAdd(&g_cur[r4.x], 1);
            int p1 = atomicAdd(&g_cur[r4.y], 1);
            int p2 = atomicAdd(&g_cur[r4.z], 1);
            int p3 = atomicAdd(&g_cur[r4.w], 1);
            g_ecv[p0] = make_int2(c4.x, __float_as_int(v4.x));
            g_ecv[p1] = make_int2(c4.y, __float_as_int(v4.y));
            g_ecv[p2] = make_int2(c4.z, __float_as_int(v4.z));
            g_ecv[p3] = make_int2(c4.w, __float_as_int(v4.w));
        }
    }
}

// ===========================================================================
// SpMM1 gather (smem-staged, fp16 in/out): h2[n] = sum vals[e] * h1[col[e]]
// ===========================================================================
__global__ __launch_bounds__(256) void spmm1_gather_kernel() {
    __shared__ int2 scv[8][32];

    int warp = threadIdx.x >> 5;
    int lane = threadIdx.x & 31;
    int node = blockIdx.x * 8 + warp;
    if (node >= N_NODES) return;

    int start = g_off[node];
    int end   = g_off[node + 1];

    float4 acc = make_float4(0.f, 0.f, 0.f, 0.f);

    for (int base = start; base < end; base += 32) {
        int m  = end - base; if (m > 32) m = 32;
        int mp = (m + 7) & ~7;
        int2 cv = make_int2(node, 0);
        if (lane < m) cv = g_ecv[base + lane];
        scv[warp][lane] = cv;
        __syncwarp();

        for (int t0 = 0; t0 < mp; t0 += 8) {
            uint2 s[8];
#pragma unroll
            for (int j = 0; j < 8; j++) {
                int c = scv[warp][t0 + j].x;
                s[j] = *((const uint2*)(g_h1h + (size_t)c * HID) + lane);
            }
#pragma unroll
            for (int j = 0; j < 8; j++) {
                float v = __int_as_float(scv[warp][t0 + j].y);
                float2 f0 = __half22float2(*(__half2*)&s[j].x);
                float2 f1 = __half22float2(*(__half2*)&s[j].y);
                acc.x = fmaf(v, f0.x, acc.x);
                acc.y = fmaf(v, f0.y, acc.y);
                acc.z = fmaf(v, f1.x, acc.z);
                acc.w = fmaf(v, f1.y, acc.w);
            }
        }
        __syncwarp();
    }

    __half2 h0 = __floats2half2_rn(acc.x, acc.y);
    __half2 h1 = __floats2half2_rn(acc.z, acc.w);
    ((uint2*)(g_h2h + (size_t)node * HID))[lane] =
        make_uint2(*(uint32_t*)&h0, *(uint32_t*)&h1);
}

// ===========================================================================
// GEMM2 (fp16 MMA, fused bias+relu, fp16 input h2):
//   g_h4h[M,64] = relu(h2 + b1) @ W2h^T
// ===========================================================================
__global__ __launch_bounds__(256) void gemm2_f16_kernel(const float* __restrict__ B1) {
    __shared__ uint32_t As[128 * GROW_W];    // A: 128 x 40 halfs
    __shared__ uint32_t Bs[64 * GROW_W];     // B: 64 x 40 halfs
    __shared__ float    b1s[HID];

    const int tid  = threadIdx.x;
    const int warp = tid >> 5;
    const int lane = tid & 31;
    const int wm   = warp >> 1;
    const int wn   = warp & 1;
    const int brow = blockIdx.x * 128;
    const int grp  = lane >> 2;
    const int tig  = lane & 3;

    if (tid < HID) b1s[tid] = B1[tid];
    __syncthreads();

    float c[2][4][4];
#pragma unroll
    for (int mt = 0; mt < 2; mt++)
#pragma unroll
        for (int nt = 0; nt < 4; nt++)
#pragma unroll
            for (int i = 0; i < 4; i++) c[mt][nt][i] = 0.f;

#pragma unroll
    for (int k0 = 0; k0 < HID; k0 += 32) {
        // A: fp16 h2 -> float, bias+relu, -> fp16 smem
#pragma unroll
        for (int i = 0; i < 4; i++) {
            int f  = tid + i * 256;          // 0..1023
            int r  = f >> 3;                 // row 0..127
            int ch = f & 7;                  // 8B chunk (4 halfs)
            int gr = brow + r;
            uint2 u = make_uint2(0, 0);
            if (gr < N_NODES)
                u = *(const uint2*)(g_h2h + (size_t)gr * HID + k0 + ch * 4);
            float2 f0 = __half22float2(*(__half2*)&u.x);
            float2 f1 = __half22float2(*(__half2*)&u.y);
            int kb = k0 + ch * 4;
            f0.x = fmaxf(f0.x + b1s[kb + 0], 0.f);
            f0.y = fmaxf(f0.y + b1s[kb + 1], 0.f);
            f1.x = fmaxf(f1.x + b1s[kb + 2], 0.f);
            f1.y = fmaxf(f1.y + b1s[kb + 3], 0.f);
            __half2 h0 = __floats2half2_rn(f0.x, f0.y);
            __half2 h1 = __floats2half2_rn(f1.x, f1.y);
            As[r * GROW_W + ch * 2 + 0] = *(uint32_t*)&h0;
            As[r * GROW_W + ch * 2 + 1] = *(uint32_t*)&h1;
        }
        // B: 64 rows x 8 chunks(8B=4 halfs)
#pragma unroll
        for (int i = 0; i < 2; i++) {
            int f  = tid + i * 256;
            int r  = f >> 3;
            int ch = f & 7;
            uint2 u = *(const uint2*)(g_w2h + (size_t)r * HID + k0 + ch * 4);
            Bs[r * GROW_W + ch * 2 + 0] = u.x;
            Bs[r * GROW_W + ch * 2 + 1] = u.y;
        }
        __syncthreads();

#pragma unroll
        for (int ks = 0; ks < 2; ks++) {
            int kw = ks * 8;
            uint32_t a[2][4], bfr[4][2];
#pragma unroll
            for (int mt = 0; mt < 2; mt++) {
                int m0 = wm * 32 + mt * 16;
                a[mt][0] = As[(m0 + grp) * GROW_W + kw + tig];
                a[mt][1] = As[(m0 + grp + 8) * GROW_W + kw + tig];
                a[mt][2] = As[(m0 + grp) * GROW_W + kw + 4 + tig];
                a[mt][3] = As[(m0 + grp + 8) * GROW_W + kw + 4 + tig];
            }
#pragma unroll
            for (int nt = 0; nt < 4; nt++) {
                int n0 = wn * 32 + nt * 8;
                bfr[nt][0] = Bs[(n0 + grp) * GROW_W + kw + tig];
                bfr[nt][1] = Bs[(n0 + grp) * GROW_W + kw + 4 + tig];
            }
#pragma unroll
            for (int mt = 0; mt < 2; mt++)
#pragma unroll
                for (int nt = 0; nt < 4; nt++)
                    mma_f16(c[mt][nt], a[mt], bfr[nt]);
        }
        __syncthreads();
    }

#pragma unroll
    for (int mt = 0; mt < 2; mt++) {
        int r0 = brow + wm * 32 + mt * 16 + grp;
        int r1 = r0 + 8;
#pragma unroll
        for (int nt = 0; nt < 4; nt++) {
            int col = wn * 32 + nt * 8 + 2 * tig;
            if (r0 < N_NODES)
                *(__half2*)(g_h4h + (size_t)r0 * OUTF + col) =
                    __floats2half2_rn(c[mt][nt][0], c[mt][nt][1]);
            if (r1 < N_NODES)
                *(__half2*)(g_h4h + (size_t)r1 * OUTF + col) =
                    __floats2half2_rn(c[mt][nt][2], c[mt][nt][3]);
        }
    }
}

// ===========================================================================
// SpMM2 gather (smem-staged, fp16 reads): out[n] = b2 + sum vals*h4[col]
// ===========================================================================
__global__ __launch_bounds__(256) void spmm2_gather_kernel(const float* __restrict__ B2,
                                                           float* __restrict__ out) {
    __shared__ int2 scv[8][32];

    int warp = threadIdx.x >> 5;
    int lane = threadIdx.x & 31;
    int node = blockIdx.x * 8 + warp;
    if (node >= N_NODES) return;

    int start = g_off[node];
    int end   = g_off[node + 1];

    float2 acc = *((const float2*)B2 + lane);

    for (int base = start; base < end; base += 32) {
        int m  = end - base; if (m > 32) m = 32;
        int mp = (m + 7) & ~7;
        int2 cv = make_int2(node, 0);
        if (lane < m) cv = g_ecv[base + lane];
        scv[warp][lane] = cv;
        __syncwarp();

        for (int t0 = 0; t0 < mp; t0 += 8) {
            __half2 s[8];
#pragma unroll
            for (int j = 0; j < 8; j++) {
                int c = scv[warp][t0 + j].x;
                s[j] = *((const __half2*)(g_h4h + (size_t)c * OUTF) + lane);
            }
#pragma unroll
            for (int j = 0; j < 8; j++) {
                float v = __int_as_float(scv[warp][t0 + j].y);
                float2 f = __half22float2(s[j]);
                acc.x = fmaf(v, f.x, acc.x);
                acc.y = fmaf(v, f.y, acc.y);
            }
        }
        __syncwarp();
    }

    *((float2*)(out + (size_t)node * OUTF) + lane) = acc;
}

// ===========================================================================
extern "C" void kernel_launch(void* const* d_in, const int* in_sizes, int n_in,
                              void* d_out, int out_size) {
    const float* x       = (const float*)d_in[0];
    const float* w1      = (const float*)d_in[1];
    const float* b1      = (const float*)d_in[2];
    const float* w2      = (const float*)d_in[3];
    const float* b2      = (const float*)d_in[4];
    const int*   adj_row = (const int*)d_in[5];
    const int*   adj_col = (const int*)d_in[6];
    const float* vals    = (const float*)d_in[7];
    float*       out     = (float*)d_out;

    (void)in_sizes; (void)n_in; (void)out_size;

    cudaFuncSetAttribute(fused_gemm1_scatter_kernel,
                         cudaFuncAttributeMaxDynamicSharedMemorySize, G1_SMEM);

    // count edges per row (4/thread) + convert X / W1^T / W2^T to fp16
    csr_count_cvt_kernel<<<CNT4_BLOCKS + XCVT_BLOCKS + W1H_BLOCKS + W2H_BLOCKS, 256>>>(
        adj_row, x, w1, w2);
    // 2-phase exclusive scan -> g_off/g_cur (resets g_cnt, g_wk)
    scan_a_kernel<<<NB_SCAN, 256>>>();
    scan_c_kernel<<<NB_SCAN, 256>>>();
    // gemm1 (fp16 MMA, 128x64 tiles, 3 CTAs/SM) + work-stealing 4-wide scatter
    fused_gemm1_scatter_kernel<<<FUSED_GRID, 256, G1_SMEM>>>(adj_row, adj_col, vals);
    // h2 = A @ h1 (fp16 gathers, fp32 accum, fp16 store)
    spmm1_gather_kernel<<<(N_NODES + 7) / 8, 256>>>();
    // h4 = relu(h2 + b1) @ W2 (fp16 MMA, fp16 out)
    gemm2_f16_kernel<<<(N_NODES + 127) / 128, 256>>>(b1);
    // out = b2 + A @ h4 (fp16 gathers)
    spmm2_gather_kernel<<<(N_NODES + 7) / 8, 256>>>(b2, out);
}

// round 17
// speedup vs baseline: 1.0197x; 1.0197x over previous
#include <cuda_runtime.h>
#include <cuda_fp16.h>
#include <cstdint>

#define N_NODES 100000
#define N_EDGES 1600000
#define IN_F    256
#define HID     128
#define OUTF    64

// Scratch (device globals: allocation-free per harness rules)
__device__ __align__(16) __half g_xh[(size_t)N_NODES * IN_F];   // X (fp16)
__device__ __align__(16) __half g_h1h[(size_t)N_NODES * HID];   // X@W1 (fp16)
__device__ __align__(16) __half g_h2h[(size_t)N_NODES * HID];   // A @ h1 (fp16)
__device__ __align__(16) __half g_h4h[(size_t)N_NODES * OUTF];  // relu(.)@W2 (fp16)
__device__ __align__(16) __half g_w1h[HID * IN_F];              // W1^T (fp16, [n][k])
__device__ __align__(16) __half g_w2h[OUTF * HID];              // W2^T (fp16, [n][k])
__device__ int    g_cnt[N_NODES];                 // per-row count (reset by scan C)
__device__ int    g_off[N_NODES + 1];             // CSR offsets
__device__ int    g_cur[N_NODES];                 // scatter cursors
__device__ int    g_wk;                           // scatter work-steal counter
__device__ int2   g_ecv[N_EDGES];                 // CSR-ordered (col, val_bits)

#define NB_SCAN ((N_NODES + 255) / 256)           // 391
__device__ int    g_bsum[NB_SCAN];

__device__ __forceinline__ void mma_f16(float c[4], const uint32_t a[4], const uint32_t b[2]) {
    asm volatile(
        "mma.sync.aligned.m16n8k16.row.col.f32.f16.f16.f32 "
        "{%0,%1,%2,%3}, {%4,%5,%6,%7}, {%8,%9}, {%0,%1,%2,%3};"
        : "+f"(c[0]), "+f"(c[1]), "+f"(c[2]), "+f"(c[3])
        : "r"(a[0]), "r"(a[1]), "r"(a[2]), "r"(a[3]), "r"(b[0]), "r"(b[1]));
}

__device__ __forceinline__ void cp16(uint32_t dst_smem, const void* src, bool pred) {
    int sz = pred ? 16 : 0;
    asm volatile("cp.async.cg.shared.global [%0], [%1], 16, %2;"
                 :: "r"(dst_smem), "l"(src), "r"(sz));
}

// ===========================================================================
// Fused: CSR count (4 edges/thread, MLP=4) + X->fp16 + W1^T + W2^T converts
// ===========================================================================
#define N_EQ4        (N_EDGES / 4)                      // 400000 (exact)
#define CNT4_BLOCKS  ((N_EQ4 + 255) / 256)              // 1563
#define XCVT_BLOCKS  (N_NODES * IN_F / 4 / 256)         // 25000 (exact)
#define W1H_BLOCKS   (IN_F * HID / 4 / 256)             // 32 (exact)
#define W2H_BLOCKS   (HID * OUTF / 4 / 256)             // 8 (exact)

__global__ void csr_count_cvt_kernel(const int* __restrict__ row,
                                     const float* __restrict__ x,
                                     const float* __restrict__ w1,
                                     const float* __restrict__ w2) {
    int b = blockIdx.x;
    if (b < CNT4_BLOCKS) {
        int i = b * 256 + threadIdx.x;       // int4 index
        if (i < N_EQ4) {
            int4 r4 = ((const int4*)row)[i];
            atomicAdd(&g_cnt[r4.x], 1);
            atomicAdd(&g_cnt[r4.y], 1);
            atomicAdd(&g_cnt[r4.z], 1);
            atomicAdd(&g_cnt[r4.w], 1);
        }
    } else if (b < CNT4_BLOCKS + XCVT_BLOCKS) {
        int i = (b - CNT4_BLOCKS) * 256 + threadIdx.x;   // float4 index
        float4 v = ((const float4*)x)[i];
        __half2 h0 = __floats2half2_rn(v.x, v.y);
        __half2 h1 = __floats2half2_rn(v.z, v.w);
        ((__half2*)g_xh)[i * 2 + 0] = h0;
        ((__half2*)g_xh)[i * 2 + 1] = h1;
    } else if (b < CNT4_BLOCKS + XCVT_BLOCKS + W1H_BLOCKS) {
        int t = (b - CNT4_BLOCKS - XCVT_BLOCKS) * 256 + threadIdx.x;
        int o = t * 4;                       // = n*IN_F + k
        int n = o >> 8;
        int k = o & (IN_F - 1);
        __half2 h0 = __floats2half2_rn(__ldg(w1 + (size_t)k * HID + n),
                                       __ldg(w1 + (size_t)(k + 1) * HID + n));
        __half2 h1 = __floats2half2_rn(__ldg(w1 + (size_t)(k + 2) * HID + n),
                                       __ldg(w1 + (size_t)(k + 3) * HID + n));
        ((__half2*)(g_w1h + o))[0] = h0;
        ((__half2*)(g_w1h + o))[1] = h1;
    } else {
        int t = (b - CNT4_BLOCKS - XCVT_BLOCKS - W1H_BLOCKS) * 256 + threadIdx.x;
        int o = t * 4;                       // = n*HID + k
        int n = o >> 7;
        int k = o & (HID - 1);
        __half2 h0 = __floats2half2_rn(__ldg(w2 + (size_t)k * OUTF + n),
                                       __ldg(w2 + (size_t)(k + 1) * OUTF + n));
        __half2 h1 = __floats2half2_rn(__ldg(w2 + (size_t)(k + 2) * OUTF + n),
                                       __ldg(w2 + (size_t)(k + 3) * OUTF + n));
        ((__half2*)(g_w2h + o))[0] = h0;
        ((__half2*)(g_w2h + o))[1] = h1;
    }
}

// ===========================================================================
// Parallel scan: phase A (block sums), phase C (prefix-of-sums + local scan)
// ===========================================================================
__global__ __launch_bounds__(256) void scan_a_kernel() {
    __shared__ int red[256];
    int t = threadIdx.x;
    int i = blockIdx.x * 256 + t;
    red[t] = (i < N_NODES) ? g_cnt[i] : 0;
    __syncthreads();
#pragma unroll
    for (int d = 128; d > 0; d >>= 1) {
        if (t < d) red[t] += red[t + d];
        __syncthreads();
    }
    if (t == 0) g_bsum[blockIdx.x] = red[0];
}

__global__ __launch_bounds__(256) void scan_c_kernel() {
    __shared__ int s[256];
    __shared__ int bpre;
    int t = threadIdx.x;

    if (blockIdx.x == 0 && t == 0) g_wk = 0;   // reset scatter work counter

    // exclusive prefix of block sums (<= 391 ints, strided read + reduce)
    int partial = 0;
    for (int i = t; i < (int)blockIdx.x; i += 256) partial += g_bsum[i];
    s[t] = partial;
    __syncthreads();
#pragma unroll
    for (int d = 128; d > 0; d >>= 1) {
        if (t < d) s[t] += s[t + d];
        __syncthreads();
    }
    if (t == 0) bpre = s[0];
    __syncthreads();

    int i = blockIdx.x * 256 + t;
    int c = (i < N_NODES) ? g_cnt[i] : 0;
    s[t] = c;
    __syncthreads();
#pragma unroll
    for (int d = 1; d < 256; d <<= 1) {
        int add = (t >= d) ? s[t - d] : 0;
        __syncthreads();
        s[t] += add;
        __syncthreads();
    }
    if (i < N_NODES) {
        int off = bpre + s[t] - c;
        g_off[i] = off;
        g_cur[i] = off;
        g_cnt[i] = 0;                          // reset for next replay
        if (i == N_NODES - 1) g_off[N_NODES] = off + c;
    }
}

// ===========================================================================
// FUSED: gemm1 tiles (128M x 128N, 8 warps 4Mx2N, warp 32x64) + work-steal
// scatter. cp.async 3-STAGE pipeline (2 tiles in flight).
//   g_h1h[M,128] = Xh[M,256] @ W1h^T
// ===========================================================================
#define GROW_W    20                        // words (uint32) per smem row
#define G1_AW     (128 * GROW_W)            // 2560 words
#define G1_BW     (128 * GROW_W)            // 2560 words
#define G1_STAGE  (G1_AW + G1_BW)           // 5120 words
#define G1_STAGES 3
#define G1_SMEM   (G1_STAGES * G1_STAGE * 4)  // 61440 bytes
#define G1_ITERS  (IN_F / 32)               // 8
#define G1_BLOCKS ((N_NODES + 127) / 128)   // 782
#define EXTRA_SC  782
#define FUSED_GRID (G1_BLOCKS + EXTRA_SC)

__global__ __launch_bounds__(256, 2) void fused_gemm1_scatter_kernel(
        const int* __restrict__ row,
        const int* __restrict__ col,
        const float* __restrict__ vals) {
    extern __shared__ uint32_t smw[];
    __shared__ int sb;

    const int tid = threadIdx.x;

    if (blockIdx.x < G1_BLOCKS) {
        // ---- gemm1 role ----
        const int warp = tid >> 5;
        const int lane = tid & 31;
        const int wm   = warp >> 1;
        const int wn   = warp & 1;
        const int brow = blockIdx.x * 128;
        const int grp  = lane >> 2;
        const int tig  = lane & 3;

        const uint32_t smem_base = (uint32_t)__cvta_generic_to_shared(smw);

        float c[2][8][4];
#pragma unroll
        for (int mt = 0; mt < 2; mt++)
#pragma unroll
            for (int nt = 0; nt < 8; nt++)
#pragma unroll
                for (int i = 0; i < 4; i++) c[mt][nt][i] = 0.f;

        auto issue = [&](int it) {
            int k0 = it * 32;                        // half index
            uint32_t st = smem_base + (uint32_t)(it % G1_STAGES) * G1_STAGE * 4;
#pragma unroll
            for (int i = 0; i < 2; i++) {
                int f  = tid + i * 256;
                int r  = f >> 2;                     // 0..127
                int ch = f & 3;                      // 16B chunk
                int gr = brow + r;
                bool ok = gr < N_NODES;
                const __half* asrc = g_xh + (size_t)(ok ? gr : 0) * IN_F + k0 + ch * 8;
                cp16(st + (uint32_t)(r * GROW_W + ch * 4) * 4, asrc, ok);
                const __half* bsrc = g_w1h + (size_t)r * IN_F + k0 + ch * 8;
                cp16(st + (uint32_t)(G1_AW + r * GROW_W + ch * 4) * 4, bsrc, true);
            }
            asm volatile("cp.async.commit_group;" ::: "memory");
        };

        issue(0);
        issue(1);

        for (int it = 0; it < G1_ITERS; it++) {
            if (it + 2 < G1_ITERS) {
                issue(it + 2);
                asm volatile("cp.async.wait_group 2;" ::: "memory");
            } else if (it + 1 < G1_ITERS) {
                asm volatile("cp.async.wait_group 1;" ::: "memory");
            } else {
                asm volatile("cp.async.wait_group 0;" ::: "memory");
            }
            __syncthreads();

            const uint32_t* As = smw + (it % G1_STAGES) * G1_STAGE;
            const uint32_t* Bs = As + G1_AW;

#pragma unroll
            for (int ks = 0; ks < 2; ks++) {         // two k16 steps per BK=32
                int kw = ks * 8;
                uint32_t a[2][4], bfr[8][2];
#pragma unroll
                for (int mt = 0; mt < 2; mt++) {
                    int m0 = wm * 32 + mt * 16;
                    a[mt][0] = As[(m0 + grp) * GROW_W + kw + tig];
                    a[mt][1] = As[(m0 + grp + 8) * GROW_W + kw + tig];
                    a[mt][2] = As[(m0 + grp) * GROW_W + kw + 4 + tig];
                    a[mt][3] = As[(m0 + grp + 8) * GROW_W + kw + 4 + tig];
                }
#pragma unroll
                for (int nt = 0; nt < 8; nt++) {
                    int n0 = wn * 64 + nt * 8;
                    bfr[nt][0] = Bs[(n0 + grp) * GROW_W + kw + tig];
                    bfr[nt][1] = Bs[(n0 + grp) * GROW_W + kw + 4 + tig];
                }
#pragma unroll
                for (int mt = 0; mt < 2; mt++)
#pragma unroll
                    for (int nt = 0; nt < 8; nt++)
                        mma_f16(c[mt][nt], a[mt], bfr[nt]);
            }
            __syncthreads();
        }

#pragma unroll
        for (int mt = 0; mt < 2; mt++) {
            int r0 = brow + wm * 32 + mt * 16 + grp;
            int r1 = r0 + 8;
#pragma unroll
            for (int nt = 0; nt < 8; nt++) {
                int col2 = wn * 64 + nt * 8 + 2 * tig;
                if (r0 < N_NODES)
                    *(__half2*)(g_h1h + (size_t)r0 * HID + col2) =
                        __floats2half2_rn(c[mt][nt][0], c[mt][nt][1]);
                if (r1 < N_NODES)
                    *(__half2*)(g_h1h + (size_t)r1 * HID + col2) =
                        __floats2half2_rn(c[mt][nt][2], c[mt][nt][3]);
            }
        }
    }

    // ---- scatter role (work-stealing; gemm CTAs fall through when done) ----
    for (;;) {
        __syncthreads();
        if (tid == 0) sb = atomicAdd(&g_wk, 1024);
        __syncthreads();
        int base = sb;
        if (base >= N_EDGES) return;
        int e0 = base + tid * 4;
        if (e0 < N_EDGES) {                  // N_EDGES % 4 == 0 -> whole quad valid
            int4   r4 = *(const int4*)(row + e0);
            int4   c4 = *(const int4*)(col + e0);
            float4 v4 = *(const float4*)(vals + e0);
            int p0 = atomicAdd(&g_cur[r4.x], 1);
            int p1 = atomicAdd(&g_cur[r4.y], 1);
            int p2 = atomicAdd(&g_cur[r4.z], 1);
            int p3 = atomicAdd(&g_cur[r4.w], 1);
            g_ecv[p0] = make_int2(c4.x, __float_as_int(v4.x));
            g_ecv[p1] = make_int2(c4.y, __float_as_int(v4.y));
            g_ecv[p2] = make_int2(c4.z, __float_as_int(v4.z));
            g_ecv[p3] = make_int2(c4.w, __float_as_int(v4.w));
        }
    }
}

// ===========================================================================
// SpMM1 gather (smem-staged, fp16 in/out): h2[n] = sum vals[e] * h1[col[e]]
// ===========================================================================
__global__ __launch_bounds__(256) void spmm1_gather_kernel() {
    __shared__ int2 scv[8][32];

    int warp = threadIdx.x >> 5;
    int lane = threadIdx.x & 31;
    int node = blockIdx.x * 8 + warp;
    if (node >= N_NODES) return;

    int start = g_off[node];
    int end   = g_off[node + 1];

    float4 acc = make_float4(0.f, 0.f, 0.f, 0.f);

    for (int base = start; base < end; base += 32) {
        int m  = end - base; if (m > 32) m = 32;
        int mp = (m + 7) & ~7;
        int2 cv = make_int2(node, 0);
        if (lane < m) cv = g_ecv[base + lane];
        scv[warp][lane] = cv;
        __syncwarp();

        for (int t0 = 0; t0 < mp; t0 += 8) {
            uint2 s[8];
#pragma unroll
            for (int j = 0; j < 8; j++) {
                int c = scv[warp][t0 + j].x;
                s[j] = *((const uint2*)(g_h1h + (size_t)c * HID) + lane);
            }
#pragma unroll
            for (int j = 0; j < 8; j++) {
                float v = __int_as_float(scv[warp][t0 + j].y);
                float2 f0 = __half22float2(*(__half2*)&s[j].x);
                float2 f1 = __half22float2(*(__half2*)&s[j].y);
                acc.x = fmaf(v, f0.x, acc.x);
                acc.y = fmaf(v, f0.y, acc.y);
                acc.z = fmaf(v, f1.x, acc.z);
                acc.w = fmaf(v, f1.y, acc.w);
            }
        }
        __syncwarp();
    }

    __half2 h0 = __floats2half2_rn(acc.x, acc.y);
    __half2 h1 = __floats2half2_rn(acc.z, acc.w);
    ((uint2*)(g_h2h + (size_t)node * HID))[lane] =
        make_uint2(*(uint32_t*)&h0, *(uint32_t*)&h1);
}

// ===========================================================================
// GEMM2 (fp16 MMA, fused bias+relu, fp16 input h2):
//   g_h4h[M,64] = relu(h2 + b1) @ W2h^T
// ===========================================================================
__global__ __launch_bounds__(256) void gemm2_f16_kernel(const float* __restrict__ B1) {
    __shared__ uint32_t As[128 * GROW_W];    // A: 128 x 40 halfs
    __shared__ uint32_t Bs[64 * GROW_W];     // B: 64 x 40 halfs
    __shared__ float    b1s[HID];

    const int tid  = threadIdx.x;
    const int warp = tid >> 5;
    const int lane = tid & 31;
    const int wm   = warp >> 1;
    const int wn   = warp & 1;
    const int brow = blockIdx.x * 128;
    const int grp  = lane >> 2;
    const int tig  = lane & 3;

    if (tid < HID) b1s[tid] = B1[tid];
    __syncthreads();

    float c[2][4][4];
#pragma unroll
    for (int mt = 0; mt < 2; mt++)
#pragma unroll
        for (int nt = 0; nt < 4; nt++)
#pragma unroll
            for (int i = 0; i < 4; i++) c[mt][nt][i] = 0.f;

#pragma unroll
    for (int k0 = 0; k0 < HID; k0 += 32) {
        // A: fp16 h2 -> float, bias+relu, -> fp16 smem
#pragma unroll
        for (int i = 0; i < 4; i++) {
            int f  = tid + i * 256;          // 0..1023
            int r  = f >> 3;                 // row 0..127
            int ch = f & 7;                  // 8B chunk (4 halfs)
            int gr = brow + r;
            uint2 u = make_uint2(0, 0);
            if (gr < N_NODES)
                u = *(const uint2*)(g_h2h + (size_t)gr * HID + k0 + ch * 4);
            float2 f0 = __half22float2(*(__half2*)&u.x);
            float2 f1 = __half22float2(*(__half2*)&u.y);
            int kb = k0 + ch * 4;
            f0.x = fmaxf(f0.x + b1s[kb + 0], 0.f);
            f0.y = fmaxf(f0.y + b1s[kb + 1], 0.f);
            f1.x = fmaxf(f1.x + b1s[kb + 2], 0.f);
            f1.y = fmaxf(f1.y + b1s[kb + 3], 0.f);
            __half2 h0 = __floats2half2_rn(f0.x, f0.y);
            __half2 h1 = __floats2half2_rn(f1.x, f1.y);
            As[r * GROW_W + ch * 2 + 0] = *(uint32_t*)&h0;
            As[r * GROW_W + ch * 2 + 1] = *(uint32_t*)&h1;
        }
        // B: 64 rows x 8 chunks(8B=4 halfs)
#pragma unroll
        for (int i = 0; i < 2; i++) {
            int f  = tid + i * 256;
            int r  = f >> 3;
            int ch = f & 7;
            uint2 u = *(const uint2*)(g_w2h + (size_t)r * HID + k0 + ch * 4);
            Bs[r * GROW_W + ch * 2 + 0] = u.x;
            Bs[r * GROW_W + ch * 2 + 1] = u.y;
        }
        __syncthreads();

#pragma unroll
        for (int ks = 0; ks < 2; ks++) {
            int kw = ks * 8;
            uint32_t a[2][4], bfr[4][2];
#pragma unroll
            for (int mt = 0; mt < 2; mt++) {
                int m0 = wm * 32 + mt * 16;
                a[mt][0] = As[(m0 + grp) * GROW_W + kw + tig];
                a[mt][1] = As[(m0 + grp + 8) * GROW_W + kw + tig];
                a[mt][2] = As[(m0 + grp) * GROW_W + kw + 4 + tig];
                a[mt][3] = As[(m0 + grp + 8) * GROW_W + kw + 4 + tig];
            }
#pragma unroll
            for (int nt = 0; nt < 4; nt++) {
                int n0 = wn * 32 + nt * 8;
                bfr[nt][0] = Bs[(n0 + grp) * GROW_W + kw + tig];
                bfr[nt][1] = Bs[(n0 + grp) * GROW_W + kw + 4 + tig];
            }
#pragma unroll
            for (int mt = 0; mt < 2; mt++)
#pragma unroll
                for (int nt = 0; nt < 4; nt++)
                    mma_f16(c[mt][nt], a[mt], bfr[nt]);
        }
        __syncthreads();
    }

#pragma unroll
    for (int mt = 0; mt < 2; mt++) {
        int r0 = brow + wm * 32 + mt * 16 + grp;
        int r1 = r0 + 8;
#pragma unroll
        for (int nt = 0; nt < 4; nt++) {
            int col = wn * 32 + nt * 8 + 2 * tig;
            if (r0 < N_NODES)
                *(__half2*)(g_h4h + (size_t)r0 * OUTF + col) =
                    __floats2half2_rn(c[mt][nt][0], c[mt][nt][1]);
            if (r1 < N_NODES)
                *(__half2*)(g_h4h + (size_t)r1 * OUTF + col) =
                    __floats2half2_rn(c[mt][nt][2], c[mt][nt][3]);
        }
    }
}

// ===========================================================================
// SpMM2 gather (smem-staged, fp16 reads): out[n] = b2 + sum vals*h4[col]
// ===========================================================================
__global__ __launch_bounds__(256) void spmm2_gather_kernel(const float* __restrict__ B2,
                                                           float* __restrict__ out) {
    __shared__ int2 scv[8][32];

    int warp = threadIdx.x >> 5;
    int lane = threadIdx.x & 31;
    int node = blockIdx.x * 8 + warp;
    if (node >= N_NODES) return;

    int start = g_off[node];
    int end   = g_off[node + 1];

    float2 acc = *((const float2*)B2 + lane);

    for (int base = start; base < end; base += 32) {
        int m  = end - base; if (m > 32) m = 32;
        int mp = (m + 7) & ~7;
        int2 cv = make_int2(node, 0);
        if (lane < m) cv = g_ecv[base + lane];
        scv[warp][lane] = cv;
        __syncwarp();

        for (int t0 = 0; t0 < mp; t0 += 8) {
            __half2 s[8];
#pragma unroll
            for (int j = 0; j < 8; j++) {
                int c = scv[warp][t0 + j].x;
                s[j] = *((const __half2*)(g_h4h + (size_t)c * OUTF) + lane);
            }
#pragma unroll
            for (int j = 0; j < 8; j++) {
                float v = __int_as_float(scv[warp][t0 + j].y);
                float2 f = __half22float2(s[j]);
                acc.x = fmaf(v, f.x, acc.x);
                acc.y = fmaf(v, f.y, acc.y);
            }
        }
        __syncwarp();
    }

    *((float2*)(out + (size_t)node * OUTF) + lane) = acc;
}

// ===========================================================================
extern "C" void kernel_launch(void* const* d_in, const int* in_sizes, int n_in,
                              void* d_out, int out_size) {
    const float* x       = (const float*)d_in[0];
    const float* w1      = (const float*)d_in[1];
    const float* b1      = (const float*)d_in[2];
    const float* w2      = (const float*)d_in[3];
    const float* b2      = (const float*)d_in[4];
    const int*   adj_row = (const int*)d_in[5];
    const int*   adj_col = (const int*)d_in[6];
    const float* vals    = (const float*)d_in[7];
    float*       out     = (float*)d_out;

    (void)in_sizes; (void)n_in; (void)out_size;

    cudaFuncSetAttribute(fused_gemm1_scatter_kernel,
                         cudaFuncAttributeMaxDynamicSharedMemorySize, G1_SMEM);

    // count edges per row (4/thread) + convert X / W1^T / W2^T to fp16
    csr_count_cvt_kernel<<<CNT4_BLOCKS + XCVT_BLOCKS + W1H_BLOCKS + W2H_BLOCKS, 256>>>(
        adj_row, x, w1, w2);
    // 2-phase exclusive scan -> g_off/g_cur (resets g_cnt, g_wk)
    scan_a_kernel<<<NB_SCAN, 256>>>();
    scan_c_kernel<<<NB_SCAN, 256>>>();
    // gemm1 (fp16 MMA, 3-stage cp.async) + work-stealing 4-wide scatter
    fused_gemm1_scatter_kernel<<<FUSED_GRID, 256, G1_SMEM>>>(adj_row, adj_col, vals);
    // h2 = A @ h1 (fp16 gathers, fp32 accum, fp16 store)
    spmm1_gather_kernel<<<(N_NODES + 7) / 8, 256>>>();
    // h4 = relu(h2 + b1) @ W2 (fp16 MMA, fp16 out)
    gemm2_f16_kernel<<<(N_NODES + 127) / 128, 256>>>(b1);
    // out = b2 + A @ h4 (fp16 gathers)
    spmm2_gather_kernel<<<(N_NODES + 7) / 8, 256>>>(b2, out);
}